// round 10
// baseline (speedup 1.0000x reference)
#include <cuda_runtime.h>
#include <math.h>

#define NC 24
#define B_   32
#define H4_  128
#define W4_  128
#define H5_  64
#define W5_  64
#define T4_  200
#define T5_  100

#define HW4  (H4_*W4_)          // 16384
#define HW5  (H5_*W5_)          // 4096
#define N4_  (B_*HW4)           // 524288
#define N5_  (B_*HW5)           // 131072
#define NT4  (B_*T4_)           // 6400
#define NT5  (B_*T5_)           // 3200
#define NTT  (NT4+NT5)          // 9600

#define NFG       (NTT*6)             // 57600 focal groups (4 classes each)
#define FOCAL_END (NTT + NFG)         // 67200
#define NSTR      ((N4_+N5_)/8)       // 81920 vec8 items
#define NTOTAL    (FOCAL_END + NSTR)  // 149120
#define STR5_I    (FOCAL_END + N4_/8) // 132736 (cls4/cls5 stream boundary)

#define NB 584                        // 584*256 = 149504 threads >= NTOTAL

// g_acc: [0]=sl1 [1]=focal [2]=objpos [3]=nb4 [4]=wc4 [5]=nb5 [6]=wc5
__device__ double g_acc[7];                   // zero-init; self-cleaned
__device__ unsigned int g_ticket;             // zero-init; self-cleaned
__device__ unsigned int g_gen = 1;            // generation tag
__device__ unsigned int g_cellgen[N4_ + N5_]; // zero-init; gen-tagged

#define LOG2E 1.442695040888963f
#define LN2   0.6931471805599453f
#define LUT_N 256
#define LUT_TMAX 6.0f
#define LUT_SCALE ((float)LUT_N / LUT_TMAX)   // 42.6667
#define LUT_STEP  (LUT_TMAX / (float)LUT_N)

// LUT lookup: f(t) for t >= 0 (clamped to [0, 6))
__device__ __forceinline__ float lut_eval(const float2* lut, float t) {
    float u = fminf(t, 5.999f) * LUT_SCALE;
    int i = (int)u;
    float fr = u - (float)i;
    float2 e = lut[i];
    return fmaf(fr, e.y, e.x);
}

__global__ void __launch_bounds__(256) k_main(
    const float* __restrict__ cls4, const float* __restrict__ reg4,
    const float* __restrict__ cls5, const float* __restrict__ reg5,
    const float* __restrict__ tgt4, const float* __restrict__ tgt5,
    float* __restrict__ out)
{
    const int lane = threadIdx.x & 31;
    const int warp = threadIdx.x >> 5;
    const int i = blockIdx.x * 256 + threadIdx.x;
    const unsigned int gen = g_gen;

    // ---------------- per-block LUTs: softplus(-t) and sigmoid(t), t in [0,6]
    __shared__ float2 lutS[LUT_N];   // softplus(-t): (value, delta-to-next)
    __shared__ float2 lutG[LUT_N];   // sigmoid(t):   (value, delta-to-next)
    {
        float t0 = (float)threadIdx.x * LUT_STEP;
        float t1 = t0 + LUT_STEP;
        float e0 = __expf(-t0), e1 = __expf(-t1);
        float f0 = log1pf(e0),  f1 = log1pf(e1);
        float g0 = 1.0f / (1.0f + e0), g1 = 1.0f / (1.0f + e1);
        lutS[threadIdx.x] = make_float2(f0, f1 - f0);
        lutG[threadIdx.x] = make_float2(g0, g1 - g0);
    }
    __syncthreads();

    float a_sl1 = 0.f, a_fo = 0.f, a_ob = 0.f;
    float a_nb4 = 0.f, a_wc4 = 0.f, a_nb5 = 0.f, a_wc5 = 0.f;

    if (i < NTT) {
        // ---------------- per-target: objectness + dedup + bbox -------------
        bool is4 = (i < NT4);
        int tl = is4 ? i : (i - NT4);
        int b  = is4 ? (tl / T4_) : (tl / T5_);
        const int W  = is4 ? W4_ : W5_;
        const int H  = is4 ? H4_ : H5_;
        const int hw = is4 ? HW4 : HW5;
        const float* tp  = (is4 ? tgt4 : tgt5) + (size_t)tl * 6;
        const float* cls = is4 ? cls4 : cls5;
        const float* reg = is4 ? reg4 : reg5;

        float tx  = tp[1] * (float)W;
        float ty  = tp[2] * (float)H;
        float twd = tp[3] * (float)W;
        float thd = tp[4] * (float)H;
        int gx = min(max((int)tx, 0), W - 1);
        int gy = min(max((int)ty, 0), H - 1);
        int cell = gy * W + gx;

        // objectness (exact path; only 9600 threads -> negligible MUFU)
        float obj = cls[(size_t)b * (1 + NC) * hw + cell];
        float ao = fabsf(obj);
        float so = exp2f(-ao * LOG2E);
        float l1po = LN2 * __log2f(1.0f + so);
        a_ob = fmaxf(-obj, 0.0f) + l1po;        // bce(obj, 1)
        float bce0o = fmaxf(obj, 0.0f) + l1po;  // bce(obj, 0)

        int gcell = is4 ? (b * HW4 + cell) : (N4_ + b * HW5 + cell);
        unsigned int old = atomicExch(&g_cellgen[gcell], gen);
        if (old != gen) {
            // subtract the LUT-based value the streaming pass added for this cell
            float spL = lut_eval(lutS, ao);
            float bce0L = fmaxf(obj, 0.0f) + spL;
            if (is4) { a_nb4 = -bce0L; a_wc4 = 1.0f; }
            else     { a_nb5 = -bce0L; a_wc5 = 1.0f; }
        }

        size_t rb = (size_t)b * 4 * hw + cell;
        float r0 = reg[rb];
        float r1 = reg[rb + hw];
        float r2 = reg[rb + 2 * (size_t)hw];
        float r3 = reg[rb + 3 * (size_t)hw];
        float px = fminf(fmaxf((float)gx + r0, 0.0f), (float)W);
        float py = fminf(fmaxf((float)gy + r1, 0.0f), (float)H);
        float pw = fminf(fmaxf(__expf(r2), 1.0f), (float)W) * 0.1f;
        float ph = fminf(fmaxf(__expf(r3), 1.0f), (float)H) * 0.1f;
        float d, ad, sl = 0.0f;
        d = (px - pw * 0.5f) - (tx - twd * 0.5f); ad = fabsf(d);
        sl += (ad < 1.0f) ? 0.5f * d * d : (ad - 0.5f);
        d = (py - ph * 0.5f) - (ty - thd * 0.5f); ad = fabsf(d);
        sl += (ad < 1.0f) ? 0.5f * d * d : (ad - 0.5f);
        d = (px + pw * 0.5f) - (tx + twd * 0.5f); ad = fabsf(d);
        sl += (ad < 1.0f) ? 0.5f * d * d : (ad - 0.5f);
        d = (py + ph * 0.5f) - (ty + thd * 0.5f); ad = fabsf(d);
        sl += (ad < 1.0f) ? 0.5f * d * d : (ad - 0.5f);
        a_sl1 = sl * 0.25f;
    } else if (i < FOCAL_END) {
        // ---------------- focal: 4 classes per thread, LUT math (no MUFU) ---
        int j = i - NTT;                   // 0..57599
        int t = j / 6;
        int c0 = (j - t * 6) * 4;          // 0,4,8,12,16,20
        bool is4 = (t < NT4);
        int tl = is4 ? t : (t - NT4);
        int b  = is4 ? (tl / T4_) : (tl / T5_);
        const int W  = is4 ? W4_ : W5_;
        const int H  = is4 ? H4_ : H5_;
        const int hw = is4 ? HW4 : HW5;
        const float* tp = (is4 ? tgt4 : tgt5) + (size_t)tl * 6;
        const float* cls = is4 ? cls4 : cls5;

        int   tcls = (int)tp[0];
        float tx = tp[1] * (float)W;
        float ty = tp[2] * (float)H;
        int gx = min(max((int)tx, 0), W - 1);
        int gy = min(max((int)ty, 0), H - 1);
        int cell = gy * W + gx;
        const float* base = cls + (size_t)b * (1 + NC) * hw + cell;

        float xs[4];
        #pragma unroll
        for (int k = 0; k < 4; k++)
            xs[k] = base[(size_t)(c0 + k + 1) * hw];

        #pragma unroll
        for (int k = 0; k < 4; k++) {
            float x = xs[k];
            float ax = fabsf(x);
            float sp = lut_eval(lutS, ax);          // softplus(-|x|)
            float sa = lut_eval(lutG, ax);          // sigmoid(|x|)
            bool hit = ((c0 + k) == tcls);
            float bce = (hit ? fmaxf(-x, 0.0f) : fmaxf(x, 0.0f)) + sp;
            float sx = (x >= 0.0f) ? sa : (1.0f - sa);   // sigmoid(x)
            float omp = hit ? (1.0f - sx) : sx;          // 1 - pt
            a_fo += (0.25f / (float)NC) * omp * omp * bce;
        }
    } else if (i < NTOTAL) {
        // ---------------- streaming negatives: vec8, LUT math (no MUFU) -----
        int v = i - FOCAL_END;
        const int NV8_4 = N4_ / 8;                  // 65536
        float4 x0, x1;
        bool is4 = (v < NV8_4);
        if (is4) {
            int b = v >> 11;                        // 2048 vec8 / image
            int pos = (v & 2047) * 8;
            const float* p = cls4 + (size_t)b * (1 + NC) * HW4 + pos;
            x0 = *(const float4*)p;
            x1 = *(const float4*)(p + 4);
        } else {
            int v5 = v - NV8_4;
            int b = v5 >> 9;                        // 512 vec8 / image
            int pos = (v5 & 511) * 8;
            const float* p = cls5 + (size_t)b * (1 + NC) * HW5 + pos;
            x0 = *(const float4*)p;
            x1 = *(const float4*)(p + 4);
        }
        float sum = 0.0f;
        #pragma unroll
        for (int k = 0; k < 8; k++) {
            float x = (k < 4) ? ((k == 0) ? x0.x : (k == 1) ? x0.y : (k == 2) ? x0.z : x0.w)
                              : ((k == 4) ? x1.x : (k == 5) ? x1.y : (k == 6) ? x1.z : x1.w);
            sum += fmaxf(x, 0.0f) + lut_eval(lutS, fabsf(x));
        }
        if (is4) a_nb4 = sum; else a_nb5 = sum;
    }

    // ---------------- section-aware reduction (boundaries warp-aligned) -----
    __shared__ float sh[7][8];
    if (threadIdx.x < 56) ((float*)sh)[threadIdx.x] = 0.0f;
    __syncthreads();

    const int wi0 = blockIdx.x * 256 + warp * 32;   // first i of this warp
    if (wi0 < NTT) {
        #pragma unroll
        for (int off = 16; off > 0; off >>= 1) {
            a_sl1 += __shfl_down_sync(0xFFFFFFFFu, a_sl1, off);
            a_ob  += __shfl_down_sync(0xFFFFFFFFu, a_ob,  off);
        }
        if (wi0 < NT4) {
            #pragma unroll
            for (int off = 16; off > 0; off >>= 1) {
                a_nb4 += __shfl_down_sync(0xFFFFFFFFu, a_nb4, off);
                a_wc4 += __shfl_down_sync(0xFFFFFFFFu, a_wc4, off);
            }
            if (lane == 0) { sh[0][warp] = a_sl1; sh[2][warp] = a_ob;
                             sh[3][warp] = a_nb4; sh[4][warp] = a_wc4; }
        } else {
            #pragma unroll
            for (int off = 16; off > 0; off >>= 1) {
                a_nb5 += __shfl_down_sync(0xFFFFFFFFu, a_nb5, off);
                a_wc5 += __shfl_down_sync(0xFFFFFFFFu, a_wc5, off);
            }
            if (lane == 0) { sh[0][warp] = a_sl1; sh[2][warp] = a_ob;
                             sh[5][warp] = a_nb5; sh[6][warp] = a_wc5; }
        }
    } else if (wi0 < FOCAL_END) {
        #pragma unroll
        for (int off = 16; off > 0; off >>= 1)
            a_fo += __shfl_down_sync(0xFFFFFFFFu, a_fo, off);
        if (lane == 0) sh[1][warp] = a_fo;
    } else if (wi0 < NTOTAL) {
        if (wi0 < STR5_I) {
            #pragma unroll
            for (int off = 16; off > 0; off >>= 1)
                a_nb4 += __shfl_down_sync(0xFFFFFFFFu, a_nb4, off);
            if (lane == 0) sh[3][warp] = a_nb4;
        } else {
            #pragma unroll
            for (int off = 16; off > 0; off >>= 1)
                a_nb5 += __shfl_down_sync(0xFFFFFFFFu, a_nb5, off);
            if (lane == 0) sh[5][warp] = a_nb5;
        }
    }
    __syncthreads();

    if (warp < 7) {
        float a = (lane < 8) ? sh[warp][lane] : 0.0f;
        #pragma unroll
        for (int off = 4; off > 0; off >>= 1)
            a += __shfl_down_sync(0xFFFFFFFFu, a, off);
        if (lane == 0 && a != 0.0f) atomicAdd(&g_acc[warp], (double)a);
    }

    // ---------------- last-block finalize (self-cleaning) -------------------
    if (threadIdx.x == 0) {
        __threadfence();
        unsigned int old = atomicAdd(&g_ticket, 1u);
        if (old == NB - 1) {
            __threadfence();
            volatile double* acc = g_acc;
            double n  = (double)NTT;
            double lb = acc[0] / n;
            double lc = acc[1] / n;
            double lo4p = acc[3] / ((double)N4_ - acc[4]);
            double lo5p = acc[5] / ((double)N5_ - acc[6]);
            double lo = (acc[2] + 0.5 * (lo4p + lo5p)) / ((double)(N4_ + N5_) + 1e-8);
            out[0] = (float)(lb + lo + lc);
            out[1] = (float)lb;
            out[2] = (float)lo;
            out[3] = (float)lc;
            #pragma unroll
            for (int k = 0; k < 7; k++) acc[k] = 0.0;
            g_gen = gen + 1u;
            __threadfence();
            *(volatile unsigned int*)&g_ticket = 0u;
        }
    }
}

extern "C" void kernel_launch(void* const* d_in, const int* in_sizes, int n_in,
                              void* d_out, int out_size) {
    const float* cls4 = (const float*)d_in[0];
    const float* reg4 = (const float*)d_in[1];
    const float* cls5 = (const float*)d_in[2];
    const float* reg5 = (const float*)d_in[3];
    const float* tgt4 = (const float*)d_in[4];
    const float* tgt5 = (const float*)d_in[5];
    float* out = (float*)d_out;

    k_main<<<NB, 256>>>(cls4, reg4, cls5, reg5, tgt4, tgt5, out);
}

// round 11
// speedup vs baseline: 1.1628x; 1.1628x over previous
#include <cuda_runtime.h>
#include <math.h>

#define NC 24
#define B_   32
#define H4_  128
#define W4_  128
#define H5_  64
#define W5_  64
#define T4_  200
#define T5_  100

#define HW4  (H4_*W4_)          // 16384
#define HW5  (H5_*W5_)          // 4096
#define N4_  (B_*HW4)           // 524288
#define N5_  (B_*HW5)           // 131072
#define NT4  (B_*T4_)           // 6400
#define NT5  (B_*T5_)           // 3200
#define NTT  (NT4+NT5)          // 9600

#define NFG       (NTT*3)             // 28800 focal groups (8 classes each)
#define FOCAL_END (NTT + NFG)         // 38400
#define NSTR      ((N4_+N5_)/8)       // 81920 vec8 items
#define NTOTAL    (FOCAL_END + NSTR)  // 120320
#define STR5_I    (FOCAL_END + N4_/8) // 103936 (cls4/cls5 stream boundary)

#define NB (NTOTAL/256)               // 470 blocks, exact

// g_acc: [0]=sl1 [1]=focal [2]=objpos [3]=nb4 [4]=wc4 [5]=nb5 [6]=wc5
__device__ double g_acc[7];                   // zero-init; self-cleaned
__device__ unsigned int g_ticket;             // zero-init; self-cleaned
__device__ unsigned int g_gen = 1;            // generation tag
__device__ unsigned int g_cellgen[N4_ + N5_]; // zero-init; gen-tagged

#define LOG2E 1.442695040888963f
#define LN2   0.6931471805599453f

__global__ void __launch_bounds__(256) k_main(
    const float* __restrict__ cls4, const float* __restrict__ reg4,
    const float* __restrict__ cls5, const float* __restrict__ reg5,
    const float* __restrict__ tgt4, const float* __restrict__ tgt5,
    float* __restrict__ out)
{
    const int lane = threadIdx.x & 31;
    const int warp = threadIdx.x >> 5;
    const int i = blockIdx.x * 256 + threadIdx.x;
    const unsigned int gen = g_gen;

    float a_sl1 = 0.f, a_fo = 0.f, a_ob = 0.f;
    float a_nb4 = 0.f, a_wc4 = 0.f, a_nb5 = 0.f, a_wc5 = 0.f;

    if (i < NTT) {
        // ---------------- per-target: objectness + dedup + bbox -------------
        bool is4 = (i < NT4);
        int tl = is4 ? i : (i - NT4);
        int b  = is4 ? (tl / T4_) : (tl / T5_);
        const int W  = is4 ? W4_ : W5_;
        const int H  = is4 ? H4_ : H5_;
        const int hw = is4 ? HW4 : HW5;
        const float* tp  = (is4 ? tgt4 : tgt5) + (size_t)tl * 6;
        const float* cls = is4 ? cls4 : cls5;
        const float* reg = is4 ? reg4 : reg5;

        float tx  = tp[1] * (float)W;
        float ty  = tp[2] * (float)H;
        float twd = tp[3] * (float)W;
        float thd = tp[4] * (float)H;
        int gx = min(max((int)tx, 0), W - 1);
        int gy = min(max((int)ty, 0), H - 1);
        int cell = gy * W + gx;

        float obj = cls[(size_t)b * (1 + NC) * hw + cell];
        float ao = fabsf(obj);
        float so = exp2f(-ao * LOG2E);
        float l1po = LN2 * __log2f(1.0f + so);
        a_ob = fmaxf(-obj, 0.0f) + l1po;        // bce(obj, 1)
        float bce0o = fmaxf(obj, 0.0f) + l1po;  // bce(obj, 0)

        int gcell = is4 ? (b * HW4 + cell) : (N4_ + b * HW5 + cell);
        unsigned int old = atomicExch(&g_cellgen[gcell], gen);
        if (old != gen) {
            if (is4) { a_nb4 = -bce0o; a_wc4 = 1.0f; }
            else     { a_nb5 = -bce0o; a_wc5 = 1.0f; }
        }

        size_t rb = (size_t)b * 4 * hw + cell;
        float r0 = reg[rb];
        float r1 = reg[rb + hw];
        float r2 = reg[rb + 2 * (size_t)hw];
        float r3 = reg[rb + 3 * (size_t)hw];
        float px = fminf(fmaxf((float)gx + r0, 0.0f), (float)W);
        float py = fminf(fmaxf((float)gy + r1, 0.0f), (float)H);
        float pw = fminf(fmaxf(__expf(r2), 1.0f), (float)W) * 0.1f;
        float ph = fminf(fmaxf(__expf(r3), 1.0f), (float)H) * 0.1f;
        float d, ad, sl = 0.0f;
        d = (px - pw * 0.5f) - (tx - twd * 0.5f); ad = fabsf(d);
        sl += (ad < 1.0f) ? 0.5f * d * d : (ad - 0.5f);
        d = (py - ph * 0.5f) - (ty - thd * 0.5f); ad = fabsf(d);
        sl += (ad < 1.0f) ? 0.5f * d * d : (ad - 0.5f);
        d = (px + pw * 0.5f) - (tx + twd * 0.5f); ad = fabsf(d);
        sl += (ad < 1.0f) ? 0.5f * d * d : (ad - 0.5f);
        d = (py + ph * 0.5f) - (ty + thd * 0.5f); ad = fabsf(d);
        sl += (ad < 1.0f) ? 0.5f * d * d : (ad - 0.5f);
        a_sl1 = sl * 0.25f;
    } else if (i < FOCAL_END) {
        // ---------------- focal: 8 classes per thread (3 threads/target) ----
        int j = i - NTT;                   // 0..28799
        int t = j / 3;
        int c0 = (j - t * 3) * 8;          // 0, 8, 16
        bool is4 = (t < NT4);
        int tl = is4 ? t : (t - NT4);
        int b  = is4 ? (tl / T4_) : (tl / T5_);
        const int W  = is4 ? W4_ : W5_;
        const int H  = is4 ? H4_ : H5_;
        const int hw = is4 ? HW4 : HW5;
        const float* tp = (is4 ? tgt4 : tgt5) + (size_t)tl * 6;
        const float* cls = is4 ? cls4 : cls5;

        int   tcls = (int)tp[0];
        float tx = tp[1] * (float)W;
        float ty = tp[2] * (float)H;
        int gx = min(max((int)tx, 0), W - 1);
        int gy = min(max((int)ty, 0), H - 1);
        int cell = gy * W + gx;
        const float* base = cls + (size_t)b * (1 + NC) * hw + cell;

        // 8 independent scattered loads (batched MLP)
        float xs[8];
        #pragma unroll
        for (int k = 0; k < 8; k++)
            xs[k] = base[(size_t)(c0 + k + 1) * hw];

        #pragma unroll
        for (int k = 0; k < 8; k++) {
            float x = xs[k];
            float ax = fabsf(x);
            float s  = exp2f(-ax * LOG2E);          // e^{-|x|}
            float r  = __fdividef(1.0f, 1.0f + s);  // sigmoid(|x|)
            float l1p = LN2 * __log2f(1.0f + s);    // log1p(e^{-|x|})
            float sp = r, sn = s * r;
            bool hit = ((c0 + k) == tcls);
            float bce = fmaxf(hit ? -x : x, 0.0f) + l1p;
            float sig_x  = (x >= 0.0f) ? sp : sn;   // sigmoid(x)
            float sig_mx = (x >= 0.0f) ? sn : sp;   // sigmoid(-x)
            float omp = hit ? sig_mx : sig_x;       // 1 - pt
            a_fo += (0.25f / (float)NC) * omp * omp * bce;
        }
    } else {
        // ---------------- streaming negatives: vec8 -------------------------
        int v = i - FOCAL_END;
        const int NV8_4 = N4_ / 8;                  // 65536
        float4 x0, x1;
        bool is4 = (v < NV8_4);
        if (is4) {
            int b = v >> 11;                        // 2048 vec8 / image
            int pos = (v & 2047) * 8;
            const float* p = cls4 + (size_t)b * (1 + NC) * HW4 + pos;
            x0 = *(const float4*)p;
            x1 = *(const float4*)(p + 4);
        } else {
            int v5 = v - NV8_4;
            int b = v5 >> 9;                        // 512 vec8 / image
            int pos = (v5 & 511) * 8;
            const float* p = cls5 + (size_t)b * (1 + NC) * HW5 + pos;
            x0 = *(const float4*)p;
            x1 = *(const float4*)(p + 4);
        }
        float m = fmaxf(x0.x, 0.0f) + fmaxf(x0.y, 0.0f) +
                  fmaxf(x0.z, 0.0f) + fmaxf(x0.w, 0.0f) +
                  fmaxf(x1.x, 0.0f) + fmaxf(x1.y, 0.0f) +
                  fmaxf(x1.z, 0.0f) + fmaxf(x1.w, 0.0f);
        float p0 = 1.0f + exp2f(-fabsf(x0.x) * LOG2E);
        float p1 = 1.0f + exp2f(-fabsf(x0.y) * LOG2E);
        float p2 = 1.0f + exp2f(-fabsf(x0.z) * LOG2E);
        float p3 = 1.0f + exp2f(-fabsf(x0.w) * LOG2E);
        float p4 = 1.0f + exp2f(-fabsf(x1.x) * LOG2E);
        float p5 = 1.0f + exp2f(-fabsf(x1.y) * LOG2E);
        float p6 = 1.0f + exp2f(-fabsf(x1.z) * LOG2E);
        float p7 = 1.0f + exp2f(-fabsf(x1.w) * LOG2E);
        float sum = m + LN2 * (__log2f((p0 * p1) * (p2 * p3)) +
                               __log2f((p4 * p5) * (p6 * p7)));
        if (is4) a_nb4 = sum; else a_nb5 = sum;
    }

    // ---------------- section-aware reduction (boundaries warp-aligned) -----
    __shared__ float sh[7][8];
    if (threadIdx.x < 56) ((float*)sh)[threadIdx.x] = 0.0f;
    __syncthreads();

    const int wi0 = blockIdx.x * 256 + warp * 32;   // first i of this warp
    if (wi0 < NTT) {
        #pragma unroll
        for (int off = 16; off > 0; off >>= 1) {
            a_sl1 += __shfl_down_sync(0xFFFFFFFFu, a_sl1, off);
            a_ob  += __shfl_down_sync(0xFFFFFFFFu, a_ob,  off);
        }
        if (wi0 < NT4) {
            #pragma unroll
            for (int off = 16; off > 0; off >>= 1) {
                a_nb4 += __shfl_down_sync(0xFFFFFFFFu, a_nb4, off);
                a_wc4 += __shfl_down_sync(0xFFFFFFFFu, a_wc4, off);
            }
            if (lane == 0) { sh[0][warp] = a_sl1; sh[2][warp] = a_ob;
                             sh[3][warp] = a_nb4; sh[4][warp] = a_wc4; }
        } else {
            #pragma unroll
            for (int off = 16; off > 0; off >>= 1) {
                a_nb5 += __shfl_down_sync(0xFFFFFFFFu, a_nb5, off);
                a_wc5 += __shfl_down_sync(0xFFFFFFFFu, a_wc5, off);
            }
            if (lane == 0) { sh[0][warp] = a_sl1; sh[2][warp] = a_ob;
                             sh[5][warp] = a_nb5; sh[6][warp] = a_wc5; }
        }
    } else if (wi0 < FOCAL_END) {
        #pragma unroll
        for (int off = 16; off > 0; off >>= 1)
            a_fo += __shfl_down_sync(0xFFFFFFFFu, a_fo, off);
        if (lane == 0) sh[1][warp] = a_fo;
    } else {
        if (wi0 < STR5_I) {
            #pragma unroll
            for (int off = 16; off > 0; off >>= 1)
                a_nb4 += __shfl_down_sync(0xFFFFFFFFu, a_nb4, off);
            if (lane == 0) sh[3][warp] = a_nb4;
        } else {
            #pragma unroll
            for (int off = 16; off > 0; off >>= 1)
                a_nb5 += __shfl_down_sync(0xFFFFFFFFu, a_nb5, off);
            if (lane == 0) sh[5][warp] = a_nb5;
        }
    }
    __syncthreads();

    if (warp < 7) {
        float a = (lane < 8) ? sh[warp][lane] : 0.0f;
        #pragma unroll
        for (int off = 4; off > 0; off >>= 1)
            a += __shfl_down_sync(0xFFFFFFFFu, a, off);
        if (lane == 0 && a != 0.0f) atomicAdd(&g_acc[warp], (double)a);
    }

    // ---------------- last-block finalize (self-cleaning) -------------------
    if (threadIdx.x == 0) {
        __threadfence();
        unsigned int old = atomicAdd(&g_ticket, 1u);
        if (old == NB - 1) {
            __threadfence();
            volatile double* acc = g_acc;
            double n  = (double)NTT;
            double lb = acc[0] / n;
            double lc = acc[1] / n;
            double lo4p = acc[3] / ((double)N4_ - acc[4]);
            double lo5p = acc[5] / ((double)N5_ - acc[6]);
            double lo = (acc[2] + 0.5 * (lo4p + lo5p)) / ((double)(N4_ + N5_) + 1e-8);
            out[0] = (float)(lb + lo + lc);
            out[1] = (float)lb;
            out[2] = (float)lo;
            out[3] = (float)lc;
            #pragma unroll
            for (int k = 0; k < 7; k++) acc[k] = 0.0;
            g_gen = gen + 1u;
            __threadfence();
            *(volatile unsigned int*)&g_ticket = 0u;
        }
    }
}

extern "C" void kernel_launch(void* const* d_in, const int* in_sizes, int n_in,
                              void* d_out, int out_size) {
    const float* cls4 = (const float*)d_in[0];
    const float* reg4 = (const float*)d_in[1];
    const float* cls5 = (const float*)d_in[2];
    const float* reg5 = (const float*)d_in[3];
    const float* tgt4 = (const float*)d_in[4];
    const float* tgt5 = (const float*)d_in[5];
    float* out = (float*)d_out;

    k_main<<<NB, 256>>>(cls4, reg4, cls5, reg5, tgt4, tgt5, out);
}